// round 8
// baseline (speedup 1.0000x reference)
#include <cuda_runtime.h>

#define ROWS 84
#define SLEN 131072
#define BPR 16                    // blocks per row -> 1344 blocks
#define THREADS 256
#define CHUNK (SLEN / BPR)        // 8192 elements
#define ITERS (CHUNK / (THREADS * 4))  // 8 float4 iterations per thread
#define GRID (ROWS * BPR)

// scratch: per (row, chunk) partial sums for ST0-side and ST1-side
__device__ float g_partial[ROWS * BPR * 2];
__device__ unsigned int g_count = 0;

__device__ __forceinline__ float sigf(float x) {
    return __fdividef(1.0f, 1.0f + __expf(-x));
}

// thread t (< 84) computes entry t of the 84-long nested-product vector for
// softmax probs p[4], exact reference order:
// t = i*21 + r ; r==0 -> p_i ; else (r-1)=j*5+s ; s==0 -> p_i p_j ; else p_i p_j p_{s-1}
__device__ __forceinline__ float prob_entry(const float* p, int t) {
    int i = t / 21;
    int r = t - i * 21;
    if (r == 0) return p[i];
    r -= 1;
    int j = r / 5;
    int s = r - j * 5;
    float pij = p[i] * p[j];
    if (s == 0) return pij;
    return pij * p[s - 1];
}

__device__ __forceinline__ void softmax4(const float* __restrict__ l, float* p) {
    float mx = fmaxf(fmaxf(l[0], l[1]), fmaxf(l[2], l[3]));
    float e0 = __expf(l[0] - mx), e1 = __expf(l[1] - mx),
          e2 = __expf(l[2] - mx), e3 = __expf(l[3] - mx);
    float inv = __fdividef(1.0f, e0 + e1 + e2 + e3);
    p[0] = e0 * inv; p[1] = e1 * inv; p[2] = e2 * inv; p[3] = e3 * inv;
}

// min 8 blocks/SM -> caps at 32 regs, keeping the memory loop at full MLP.
__global__ __launch_bounds__(THREADS, 8)
void fused_kernel(const float* __restrict__ ST0, const float* __restrict__ W0,
                  const float* __restrict__ ST1, const float* __restrict__ W1,
                  const float* __restrict__ BEV, const float* __restrict__ BEV_p,
                  const float* __restrict__ B,
                  const float* __restrict__ probs0, const float* __restrict__ probs1,
                  const float* __restrict__ probs2, const float* __restrict__ probs3,
                  const float* __restrict__ probs4,
                  float* __restrict__ out) {
    const int row = blockIdx.x / BPR;
    const int chunk = blockIdx.x - row * BPR;
    const float b = B[0];
    const float bb = b * (fmaxf(BEV_p[0], 0.0f) * BEV[0]);  // sig(b*st + bb)

    const size_t base = (size_t)row * SLEN + (size_t)chunk * CHUNK;
    const float4* st0 = (const float4*)(ST0 + base);
    const float4* w0  = (const float4*)(W0 + base);
    const float4* st1 = (const float4*)(ST1 + base);
    const float4* w1  = (const float4*)(W1 + base);

    float s0 = 0.0f, s1 = 0.0f;
    #pragma unroll
    for (int it = 0; it < ITERS; ++it) {
        const int idx = it * THREADS + threadIdx.x;
        float4 a0 = st0[idx];
        float4 c0 = w0[idx];
        float4 a1 = st1[idx];
        float4 c1 = w1[idx];
        s0 += sigf(fmaf(b, a0.x, bb)) * c0.x;
        s0 += sigf(fmaf(b, a0.y, bb)) * c0.y;
        s0 += sigf(fmaf(b, a0.z, bb)) * c0.z;
        s0 += sigf(fmaf(b, a0.w, bb)) * c0.w;
        s1 += sigf(fmaf(b, a1.x, bb)) * c1.x;
        s1 += sigf(fmaf(b, a1.y, bb)) * c1.y;
        s1 += sigf(fmaf(b, a1.z, bb)) * c1.z;
        s1 += sigf(fmaf(b, a1.w, bb)) * c1.w;
    }

    // block reduction of the two partial dot products
    #pragma unroll
    for (int o = 16; o > 0; o >>= 1) {
        s0 += __shfl_down_sync(0xFFFFFFFFu, s0, o);
        s1 += __shfl_down_sync(0xFFFFFFFFu, s1, o);
    }
    __shared__ float sh0[THREADS / 32], sh1[THREADS / 32];
    __shared__ bool is_last;
    const int warp = threadIdx.x >> 5, lane = threadIdx.x & 31;
    if (lane == 0) { sh0[warp] = s0; sh1[warp] = s1; }
    __syncthreads();
    if (threadIdx.x == 0) {
        float t0 = 0.0f, t1 = 0.0f;
        #pragma unroll
        for (int w = 0; w < THREADS / 32; ++w) { t0 += sh0[w]; t1 += sh1[w]; }
        const int slot = (row * BPR + chunk) * 2;
        g_partial[slot]     = t0;
        g_partial[slot + 1] = t1;
        __threadfence();
        unsigned int ticket = atomicAdd(&g_count, 1u);
        is_last = (ticket == GRID - 1);
    }
    __syncthreads();
    if (!is_last) return;

    // ---- last block: finalize (parallel across 84 threads; spills OK here) ----
    const int t = threadIdx.x;
    float c = 0.0f;
    if (t < ROWS) {
        float a0 = 0.0f, a1 = 0.0f;
        #pragma unroll
        for (int k = 0; k < BPR; ++k) {
            const int slot = (t * BPR + k) * 2;
            a0 += g_partial[slot];
            a1 += g_partial[slot + 1];
        }
        float p[4], e;
        softmax4(probs0, p); e = prob_entry(p, t);
        c = e * a0;
        float esum = 0.0f;
        softmax4(probs1, p); esum += prob_entry(p, t);
        softmax4(probs2, p); esum += prob_entry(p, t);
        softmax4(probs3, p); esum += prob_entry(p, t);
        softmax4(probs4, p); esum += prob_entry(p, t);
        c += esum * a1;
    }
    // block-reduce c over all 256 threads (threads >= 84 contribute 0)
    #pragma unroll
    for (int o = 16; o > 0; o >>= 1)
        c += __shfl_down_sync(0xFFFFFFFFu, c, o);
    if (lane == 0) sh0[warp] = c;
    __syncthreads();
    if (t == 0) {
        float acc = 0.0f;
        #pragma unroll
        for (int w = 0; w < THREADS / 32; ++w) acc += sh0[w];
        out[0] = acc * 0.2f;
        g_count = 0;   // reset for next graph replay
    }
}

extern "C" void kernel_launch(void* const* d_in, const int* in_sizes, int n_in,
                              void* d_out, int out_size) {
    const float* BEV   = (const float*)d_in[0];
    const float* ST0   = (const float*)d_in[1];
    const float* W0    = (const float*)d_in[2];
    const float* ST1   = (const float*)d_in[3];
    const float* W1    = (const float*)d_in[4];
    const float* p0    = (const float*)d_in[5];
    const float* p1    = (const float*)d_in[6];
    const float* p2    = (const float*)d_in[7];
    const float* p3    = (const float*)d_in[8];
    const float* p4    = (const float*)d_in[9];
    const float* BEV_p = (const float*)d_in[10];
    const float* B     = (const float*)d_in[11];
    float* out = (float*)d_out;

    fused_kernel<<<GRID, THREADS>>>(ST0, W0, ST1, W1, BEV, BEV_p, B,
                                    p0, p1, p2, p3, p4, out);
}

// round 9
// speedup vs baseline: 1.2002x; 1.2002x over previous
#include <cuda_runtime.h>

#define ROWS 84
#define SLEN 131072
#define BPR 16                    // blocks per row
#define THREADS 256
#define CHUNK (SLEN / BPR)        // 8192 elements
#define ITERS (CHUNK / (THREADS * 4))  // 8 float4 iterations per thread

// scratch: per (row, chunk) partial sums for ST0-side and ST1-side
__device__ float g_partial[ROWS * BPR * 2];

__device__ __forceinline__ float sigf(float x) {
    return __fdividef(1.0f, 1.0f + __expf(-x));
}

__global__ __launch_bounds__(THREADS)
void reduce_kernel(const float* __restrict__ ST0, const float* __restrict__ W0,
                   const float* __restrict__ ST1, const float* __restrict__ W1,
                   const float* __restrict__ BEV, const float* __restrict__ BEV_p,
                   const float* __restrict__ B) {
    const int row = blockIdx.y;
    const int chunk = blockIdx.x;
    const float b = B[0];
    const float bb = b * (fmaxf(BEV_p[0], 0.0f) * BEV[0]);  // sig(b*st + bb)

    const size_t base = (size_t)row * SLEN + (size_t)chunk * CHUNK;
    const float4* st0 = (const float4*)(ST0 + base);
    const float4* w0  = (const float4*)(W0 + base);
    const float4* st1 = (const float4*)(ST1 + base);
    const float4* w1  = (const float4*)(W1 + base);

    float s0 = 0.0f, s1 = 0.0f;
    #pragma unroll
    for (int it = 0; it < ITERS; ++it) {
        const int idx = it * THREADS + threadIdx.x;
        float4 a0 = st0[idx];
        float4 c0 = w0[idx];
        float4 a1 = st1[idx];
        float4 c1 = w1[idx];
        s0 += sigf(fmaf(b, a0.x, bb)) * c0.x;
        s0 += sigf(fmaf(b, a0.y, bb)) * c0.y;
        s0 += sigf(fmaf(b, a0.z, bb)) * c0.z;
        s0 += sigf(fmaf(b, a0.w, bb)) * c0.w;
        s1 += sigf(fmaf(b, a1.x, bb)) * c1.x;
        s1 += sigf(fmaf(b, a1.y, bb)) * c1.y;
        s1 += sigf(fmaf(b, a1.z, bb)) * c1.z;
        s1 += sigf(fmaf(b, a1.w, bb)) * c1.w;
    }

    // block reduction
    #pragma unroll
    for (int o = 16; o > 0; o >>= 1) {
        s0 += __shfl_down_sync(0xFFFFFFFFu, s0, o);
        s1 += __shfl_down_sync(0xFFFFFFFFu, s1, o);
    }
    __shared__ float sh0[THREADS / 32], sh1[THREADS / 32];
    const int warp = threadIdx.x >> 5, lane = threadIdx.x & 31;
    if (lane == 0) { sh0[warp] = s0; sh1[warp] = s1; }
    __syncthreads();
    if (threadIdx.x == 0) {
        float t0 = 0.0f, t1 = 0.0f;
        #pragma unroll
        for (int w = 0; w < THREADS / 32; ++w) { t0 += sh0[w]; t1 += sh1[w]; }
        const int slot = (row * BPR + chunk) * 2;
        g_partial[slot]     = t0;
        g_partial[slot + 1] = t1;
    }
}

// thread t (< 84) computes entry t of the 84-long nested-product vector for
// softmax probs p[4], exact reference order:
// t = i*21 + r ; r==0 -> p_i ; else (r-1)=j*5+s ; s==0 -> p_i p_j ; else p_i p_j p_{s-1}
__device__ __forceinline__ float prob_entry(const float* p, int t) {
    int i = t / 21;
    int r = t - i * 21;
    if (r == 0) return p[i];
    r -= 1;
    int j = r / 5;
    int s = r - j * 5;
    float pij = p[i] * p[j];
    if (s == 0) return pij;
    return pij * p[s - 1];
}

__device__ __forceinline__ void softmax4(const float* __restrict__ l, float* p) {
    float mx = fmaxf(fmaxf(l[0], l[1]), fmaxf(l[2], l[3]));
    float e0 = __expf(l[0] - mx), e1 = __expf(l[1] - mx),
          e2 = __expf(l[2] - mx), e3 = __expf(l[3] - mx);
    float inv = __fdividef(1.0f, e0 + e1 + e2 + e3);
    p[0] = e0 * inv; p[1] = e1 * inv; p[2] = e2 * inv; p[3] = e3 * inv;
}

__global__ __launch_bounds__(128)
void finalize_kernel(const float* __restrict__ probs0,
                     const float* __restrict__ probs1,
                     const float* __restrict__ probs2,
                     const float* __restrict__ probs3,
                     const float* __restrict__ probs4,
                     float* __restrict__ out) {
    const int t = threadIdx.x;
    float c = 0.0f;
    if (t < ROWS) {
        float a0 = 0.0f, a1 = 0.0f;
        #pragma unroll
        for (int k = 0; k < BPR; ++k) {
            const int slot = (t * BPR + k) * 2;
            a0 += g_partial[slot];
            a1 += g_partial[slot + 1];
        }
        float p[4];
        softmax4(probs0, p);
        c = prob_entry(p, t) * a0;
        float esum = 0.0f;
        softmax4(probs1, p); esum += prob_entry(p, t);
        softmax4(probs2, p); esum += prob_entry(p, t);
        softmax4(probs3, p); esum += prob_entry(p, t);
        softmax4(probs4, p); esum += prob_entry(p, t);
        c += esum * a1;
    }
    // block-reduce c over 128 threads (threads >= 84 contribute 0)
    #pragma unroll
    for (int o = 16; o > 0; o >>= 1)
        c += __shfl_down_sync(0xFFFFFFFFu, c, o);
    __shared__ float sh[4];
    const int warp = t >> 5, lane = t & 31;
    if (lane == 0) sh[warp] = c;
    __syncthreads();
    if (t == 0)
        out[0] = (sh[0] + sh[1] + sh[2] + sh[3]) * 0.2f;
}

extern "C" void kernel_launch(void* const* d_in, const int* in_sizes, int n_in,
                              void* d_out, int out_size) {
    const float* BEV   = (const float*)d_in[0];
    const float* ST0   = (const float*)d_in[1];
    const float* W0    = (const float*)d_in[2];
    const float* ST1   = (const float*)d_in[3];
    const float* W1    = (const float*)d_in[4];
    const float* p0    = (const float*)d_in[5];
    const float* p1    = (const float*)d_in[6];
    const float* p2    = (const float*)d_in[7];
    const float* p3    = (const float*)d_in[8];
    const float* p4    = (const float*)d_in[9];
    const float* BEV_p = (const float*)d_in[10];
    const float* B     = (const float*)d_in[11];
    float* out = (float*)d_out;

    dim3 grid(BPR, ROWS);
    reduce_kernel<<<grid, THREADS>>>(ST0, W0, ST1, W1, BEV, BEV_p, B);
    finalize_kernel<<<1, 128>>>(p0, p1, p2, p3, p4, out);
}